// round 13
// baseline (speedup 1.0000x reference)
#include <cuda_runtime.h>
#include <cuda_fp16.h>
#include <cstdint>
#include <cstddef>

// Problem constants
#define BB 1024
#define TT 64
#define DD 256
#define HH 512
#define LN_EPS 1e-5f

// Fused step GEMM (fp16 mma m16n8k16): C[128 m, 128 n] per CTA,
// n = 32 hcols x 4 gates. K = 768 in 12 chunks of 64 (4 k16 each).
// 256 threads = 8 warps (wm 0..1 x wn 0..3), warp tile 64m x 32n (4 mt).
// Chunks 0..7 = h (barrier-dependent), 8..11 = x (independent).
// 3-stage cp.async ring, one __syncthreads per chunk.
// Grid (16 ct, 8 mb) = 128 CTAs, 1 per SM, persistent over all 64 steps.
#define NCH 12
#define ATILE_U4 1024                   // 4 rbl x 4 k16 x 2 mt_l x 32 lanes
#define BTILE_U4 1024                   // 4 k16 x 4 wn x 2 q x 32 lanes
#define NSTG 3
#define OFF_A4(s) ((s) * ATILE_U4)
#define OFF_B4(s) (NSTG * ATILE_U4 + (s) * BTILE_U4)
#define OFF_BIAS4 (NSTG * ATILE_U4 + NSTG * BTILE_U4)
#define SMEM_BYTES ((OFF_BIAS4 + 32) * 16)    // 98816
#define NCTAS 128

// chunk schedule: x chunks first, then h chunks
#define ORD(i) ((i) < 4 ? 8 + (i) : (i) - 4)

// ---------------------------------------------------------------------------
// Scratch (device globals)
// ---------------------------------------------------------------------------
__device__ uint4 g_hp[2][(BB / 32) * (HH / 16) * 2 * 32];            // fp16 frag h
__device__ uint4 g_xp[(size_t)(BB / 32) * TT * (DD / 16) * 2 * 32];  // fp16 frag x
__device__ uint4 g_wB[16 * NCH * BTILE_U4];                          // fp16 frag W
__device__ float g_c[BB * HH];
__device__ unsigned g_bar;

__device__ __forceinline__ float sigm(float x) { return 1.0f / (1.0f + __expf(-x)); }

__device__ __forceinline__ uint32_t smem_u32(const void* p) {
    uint32_t a;
    asm("{ .reg .u64 t; cvta.to.shared.u64 t, %1; cvt.u32.u64 %0, t; }" : "=r"(a) : "l"(p));
    return a;
}

__device__ __forceinline__ uint32_t pack_h2(float a, float b) {
    __half2 h = __floats2half2_rn(a, b);
    return *(uint32_t*)&h;
}

__device__ __forceinline__ void mma_f16(float* d, const uint4& a,
                                        uint32_t b0, uint32_t b1) {
    asm volatile(
        "mma.sync.aligned.m16n8k16.row.col.f32.f16.f16.f32 "
        "{%0,%1,%2,%3}, {%4,%5,%6,%7}, {%8,%9}, {%0,%1,%2,%3};"
        : "+f"(d[0]), "+f"(d[1]), "+f"(d[2]), "+f"(d[3])
        : "r"(a.x), "r"(a.y), "r"(a.z), "r"(a.w), "r"(b0), "r"(b1));
}

__device__ __forceinline__ void cp_async16(uint32_t smem_addr, const void* gptr) {
    asm volatile("cp.async.cg.shared.global [%0], [%1], 16;"
                 :: "r"(smem_addr), "l"(gptr));
}
#define CP_COMMIT() asm volatile("cp.async.commit_group;" ::: "memory")
#define CP_WAIT(n)  asm volatile("cp.async.wait_group %0;" :: "n"(n) : "memory")

// ---------------------------------------------------------------------------
// Prep kernels (layouts identical to R10)
// ---------------------------------------------------------------------------
__global__ void prep_weights(const float* __restrict__ W_ih,
                             const float* __restrict__ W_hh) {
    const int ct = blockIdx.x;      // 0..15
    const int c  = blockIdx.y;      // 0..11
    uint4* dst = g_wB + ((size_t)ct * NCH + c) * BTILE_U4;
    for (int idx = threadIdx.x; idx < BTILE_U4; idx += blockDim.x) {
        int lane = idx & 31, q = (idx >> 5) & 1, wn = (idx >> 6) & 3, k16 = idx >> 8;
        int lq = lane >> 2, lr = lane & 3;
        uint32_t v[4];
        #pragma unroll
        for (int s = 0; s < 4; s++) {
            int nt = q * 2 + (s >> 1);
            int hi = s & 1;
            int grow = nt * HH + ct * 32 + wn * 8 + lq;
            int k = c * 64 + k16 * 16 + hi * 8 + lr * 2;
            float w0, w1;
            if (k < HH) {
                w0 = W_hh[(size_t)grow * HH + k];
                w1 = W_hh[(size_t)grow * HH + k + 1];
            } else {
                w0 = W_ih[(size_t)grow * DD + (k - HH)];
                w1 = W_ih[(size_t)grow * DD + (k - HH) + 1];
            }
            v[s] = pack_h2(w0, w1);
        }
        dst[idx] = make_uint4(v[0], v[1], v[2], v[3]);
    }
}

__global__ void prep_x(const float* __restrict__ x) {
    size_t idx = (size_t)blockIdx.x * blockDim.x + threadIdx.x;
    if (idx >= (size_t)(BB / 32) * TT * (DD / 16) * 2 * 32) return;
    int lane = (int)(idx & 31);
    int mt   = (int)((idx >> 5) & 1);
    int k16x = (int)((idx >> 6) & 15);
    int tt   = (int)((idx >> 10) & 63);
    int rowblk = (int)(idx >> 16);
    int lq = lane >> 2, lr = lane & 3;
    uint32_t v[4];
    #pragma unroll
    for (int s = 0; s < 4; s++) {
        int half = s & 1, hi = s >> 1;
        int m = rowblk * 32 + mt * 16 + half * 8 + lq;
        int d = k16x * 16 + hi * 8 + lr * 2;
        const float* src = x + ((size_t)m * TT + tt) * DD + d;
        v[s] = pack_h2(src[0], src[1]);
    }
    g_xp[idx] = make_uint4(v[0], v[1], v[2], v[3]);
}

__global__ void init_states(const float* __restrict__ h0, const float* __restrict__ c0) {
    int i = blockIdx.x * blockDim.x + threadIdx.x;
    if (i == 0) g_bar = 0;
    if (i >= BB * HH) return;
    int m = i / HH, col = i % HH;
    int rowblk = m >> 5, r5 = m & 31;
    int mt = r5 >> 4, half = (r5 >> 3) & 1, lq = r5 & 7;
    int kg = col >> 4, p = col & 15;
    int hi = p >> 3, lr = (p & 7) >> 1, lo = p & 1;
    int s = hi * 2 + half;
    size_t f4 = (((size_t)rowblk * (HH / 16) + kg) * 2 + mt) * 32 + (lq * 4 + lr);
    __half* dst = (__half*)g_hp[0];
    dst[f4 * 8 + s * 2 + lo] = __float2half_rn(h0[i]);
    g_c[i] = c0[i];
}

// ---------------------------------------------------------------------------
// Persistent fused LSTM (fp16 mma, 128x128 CTA tile, 3-stage ring).
// ---------------------------------------------------------------------------
__global__ __launch_bounds__(256, 1)
void lstm_persist(const float* __restrict__ b_ih, const float* __restrict__ b_hh,
                  const int* __restrict__ dones, float* __restrict__ out) {
    extern __shared__ uint4 sm4[];
    const uint32_t sb = smem_u32(sm4);
    float* biasS = (float*)(sm4 + OFF_BIAS4);
    const int tid  = threadIdx.x;
    const int wid  = tid >> 5;
    const int lane = tid & 31;
    const int wm   = wid >> 2;           // 0..1 (64 m-rows each)
    const int wn   = wid & 3;            // 0..3 (8 hcols x 4 gates)
    const int ct   = blockIdx.x;         // 0..15
    const int c0   = ct * 32;
    const int m0   = blockIdx.y * 128;   // 0..7 m-tiles
    const int rb0  = m0 >> 5;            // 4 rowblocks per CTA
    const int lq   = lane >> 2;
    const int lr   = lane & 3;

    if (tid < 128) {
        int gate = tid >> 5, hl = tid & 31;
        int col = gate * HH + c0 + hl;
        biasS[tid] = b_ih[col] + b_hh[col];
    }
    __syncthreads();

    for (int t = 0; t < TT; t++) {
        const uint4* __restrict__ hp_in = g_hp[t & 1];
        uint32_t* __restrict__ hp_out   = (uint32_t*)g_hp[(t + 1) & 1];

        // loader: A = 4 rowblocks x 256 uint4 (4/thread); B = 1024 uint4 (4/thread)
        auto load_tile = [&](int c, int stage) {
            const uint32_t abase = sb + OFF_A4(stage) * 16;
            const uint32_t bbase = sb + OFF_B4(stage) * 16;
            #pragma unroll
            for (int l = 0; l < 4; l++) {
                int idx = l * 256 + tid;     // 0..1023
                int rbl = idx >> 8;
                int rem = idx & 255;
                const uint4* src;
                if (c < 8)
                    src = hp_in + (size_t)(rb0 + rbl) * 2048 + c * 256 + rem;
                else
                    src = g_xp + ((size_t)(rb0 + rbl) * TT + t) * 1024 + (c - 8) * 256 + rem;
                cp_async16(abase + idx * 16, src);
            }
            const uint4* bsrc = g_wB + ((size_t)ct * NCH + c) * BTILE_U4;
            #pragma unroll
            for (int l = 0; l < 4; l++) {
                int idx = l * 256 + tid;
                cp_async16(bbase + idx * 16, bsrc + idx);
            }
            CP_COMMIT();
        };

        float acc[4][4][4];
        #pragma unroll
        for (int mt = 0; mt < 4; mt++)
            #pragma unroll
            for (int nt = 0; nt < 4; nt++)
                #pragma unroll
                for (int i = 0; i < 4; i++) acc[mt][nt][i] = 0.0f;

        // prologue: chunks 8, 9 (x) into stages 0, 1
        load_tile(ORD(0), 0);
        load_tile(ORD(1), 1);

        int stage = 0, stage2 = 2;        // stage = idx%3, stage2 = (idx+2)%3
        #pragma unroll 1
        for (int idx = 0; idx < NCH; idx++) {
            if (idx < NCH - 1) { CP_WAIT(1); } else { CP_WAIT(0); }
            __syncthreads();               // load(idx) visible; compute(idx-1) done

            if (idx == 2) {
                // grid barrier before issuing the first h-chunk load (ORD(4)=0)
                if (tid == 0) {
                    unsigned target = (unsigned)(NCTAS * t);
                    while (*(volatile unsigned*)&g_bar < target) { __nanosleep(64); }
                }
                __syncthreads();
                __threadfence();
            }
            if (idx + 2 < NCH) load_tile(ORD(idx + 2), stage2);

            const uint4* Au = sm4 + OFF_A4(stage);
            const uint4* Bu = sm4 + OFF_B4(stage);
            #pragma unroll
            for (int k16 = 0; k16 < 4; k16++) {
                uint4 a[4];
                #pragma unroll
                for (int mt = 0; mt < 4; mt++)
                    a[mt] = Au[(wm * 2 + (mt >> 1)) * 256 + k16 * 64 + (mt & 1) * 32 + lane];
                uint4 b0 = Bu[k16 * 256 + wn * 64 + lane];          // nt 0,1
                uint4 b1 = Bu[k16 * 256 + wn * 64 + 32 + lane];     // nt 2,3
                #pragma unroll
                for (int mt = 0; mt < 4; mt++) {
                    mma_f16(acc[mt][0], a[mt], b0.x, b0.y);
                    mma_f16(acc[mt][1], a[mt], b0.z, b0.w);
                    mma_f16(acc[mt][2], a[mt], b1.x, b1.y);
                    mma_f16(acc[mt][3], a[mt], b1.z, b1.w);
                }
            }
            stage  = (stage  == 2) ? 0 : stage + 1;
            stage2 = (stage2 == 2) ? 0 : stage2 + 1;
        }

        // ---- Epilogue ----
        const int kg = ct * 2 + (wn >> 1);
        #pragma unroll
        for (int mt = 0; mt < 4; mt++) {
            const int rbg = rb0 + wm * 2 + (mt >> 1);   // global rowblock
            const int mtl = mt & 1;
            #pragma unroll
            for (int half = 0; half < 2; half++) {
                const int m = m0 + wm * 64 + mt * 16 + half * 8 + lq;
                float maskn = 1.0f;
                if (t < TT - 1) maskn = 1.0f - (float)dones[(size_t)m * TT + t];
                const int hl0 = wn * 8 + lr * 2;
                const int colh0 = c0 + hl0;
                const size_t sidx0 = (size_t)m * HH + colh0;
                float2 cpv = *(float2*)(g_c + sidx0);
                float hn2[2], cn2[2];
                #pragma unroll
                for (int ci = 0; ci < 2; ci++) {
                    const int idx = half * 2 + ci;
                    const int hl = hl0 + ci;
                    float gi = acc[mt][0][idx] + biasS[0 * 32 + hl];
                    float gf = acc[mt][1][idx] + biasS[1 * 32 + hl];
                    float gg = acc[mt][2][idx] + biasS[2 * 32 + hl];
                    float go = acc[mt][3][idx] + biasS[3 * 32 + hl];
                    float cp = (ci == 0) ? cpv.x : cpv.y;
                    float cn = sigm(gf) * cp + sigm(gi) * tanhf(gg);
                    float hn = sigm(go) * tanhf(cn);
                    cn2[ci] = cn * maskn;
                    hn2[ci] = hn;
                }
                {
                    int s = (wn & 1) * 2 + half;
                    size_t f4 = (((size_t)rbg * 32 + kg) * 2 + mtl) * 32 + (lq * 4 + lr);
                    hp_out[f4 * 4 + s] = pack_h2(hn2[0] * maskn, hn2[1] * maskn);
                }
                *(float2*)(g_c + sidx0) = make_float2(cn2[0], cn2[1]);
                *(float2*)(out + ((size_t)m * TT + t) * HH + colh0) =
                    make_float2(hn2[0], hn2[1]);
            }
        }

        __threadfence();
        __syncthreads();
        if (tid == 0) atomicAdd(&g_bar, 1u);
    }
}

// ---------------------------------------------------------------------------
// Copy final states BEFORE LayerNorm: h_n = out[:, T-1, :], c_n = g_c.
// ---------------------------------------------------------------------------
__global__ void copy_states(float* __restrict__ out) {
    int i = blockIdx.x * blockDim.x + threadIdx.x;
    if (i < BB * HH) {
        const size_t base = (size_t)BB * TT * HH;
        int m = i / HH, col = i % HH;
        out[base + i]           = out[((size_t)m * TT + (TT - 1)) * HH + col];
        out[base + BB * HH + i] = g_c[i];
    }
}

// ---------------------------------------------------------------------------
// LayerNorm in-place over H=512. One 128-thread block per row.
// ---------------------------------------------------------------------------
__global__ __launch_bounds__(128)
void ln_kernel(float* __restrict__ out, const float* __restrict__ gamma,
               const float* __restrict__ beta) {
    __shared__ float red[8];
    const int row = blockIdx.x;
    const int tid = threadIdx.x;
    float* p = out + (size_t)row * HH;

    float4 v = ((const float4*)p)[tid];
    float s  = v.x + v.y + v.z + v.w;
    float sq = v.x * v.x + v.y * v.y + v.z * v.z + v.w * v.w;
    #pragma unroll
    for (int o = 16; o > 0; o >>= 1) {
        s  += __shfl_xor_sync(0xFFFFFFFFu, s, o);
        sq += __shfl_xor_sync(0xFFFFFFFFu, sq, o);
    }
    int warp = tid >> 5, lane = tid & 31;
    if (lane == 0) { red[warp] = s; red[4 + warp] = sq; }
    __syncthreads();
    s  = red[0] + red[1] + red[2] + red[3];
    sq = red[4] + red[5] + red[6] + red[7];

    float mu  = s * (1.0f / HH);
    float var = sq * (1.0f / HH) - mu * mu;
    float rr  = rsqrtf(var + LN_EPS);

    float4 gm = ((const float4*)gamma)[tid];
    float4 bt = ((const float4*)beta)[tid];
    float4 y;
    y.x = gm.x * (v.x - mu) * rr + bt.x;
    y.y = gm.y * (v.y - mu) * rr + bt.y;
    y.z = gm.z * (v.z - mu) * rr + bt.z;
    y.w = gm.w * (v.w - mu) * rr + bt.w;
    ((float4*)p)[tid] = y;
}

// ---------------------------------------------------------------------------
// Launch
// ---------------------------------------------------------------------------
extern "C" void kernel_launch(void* const* d_in, const int* in_sizes, int n_in,
                              void* d_out, int out_size) {
    const float* x     = (const float*)d_in[0];
    const float* h0    = (const float*)d_in[1];
    const float* c0    = (const float*)d_in[2];
    const float* W_ih  = (const float*)d_in[3];
    const float* W_hh  = (const float*)d_in[4];
    const float* b_ih  = (const float*)d_in[5];
    const float* b_hh  = (const float*)d_in[6];
    const float* gamma = (const float*)d_in[7];
    const float* beta  = (const float*)d_in[8];
    const int*   dones = (const int*)d_in[9];
    float* out = (float*)d_out;

    cudaFuncSetAttribute(lstm_persist, cudaFuncAttributeMaxDynamicSharedMemorySize,
                         SMEM_BYTES);

    init_states<<<(BB * HH + 255) / 256, 256>>>(h0, c0);
    prep_weights<<<dim3(16, NCH), 256>>>(W_ih, W_hh);
    {
        size_t n = (size_t)(BB / 32) * TT * (DD / 16) * 2 * 32;
        prep_x<<<(int)((n + 255) / 256), 256>>>(x);
    }

    lstm_persist<<<dim3(16, 8), 256, SMEM_BYTES>>>(b_ih, b_hh, dones, out);

    copy_states<<<(BB * HH + 255) / 256, 256>>>(out);
    ln_kernel<<<BB * TT, 128>>>(out, gamma, beta);
}

// round 14
// speedup vs baseline: 1.2599x; 1.2599x over previous
#include <cuda_runtime.h>
#include <cuda_fp16.h>
#include <cstdint>
#include <cstddef>

// Problem constants
#define BB 1024
#define TT 64
#define DD 256
#define HH 512
#define LN_EPS 1e-5f

// Fused step GEMM (fp16 mma m16n8k16): C[64 m, 128 n] per CTA,
// n = 32 hcols x 4 gates. K = 768 in 12 chunks of 64 (4 k16 each).
// 256 threads = 8 warps (wm 0..1 x wn 0..3), warp tile 32m x 32n.
// Chunks 0..7 = h (barrier-dependent), 8..11 = x (independent).
// 3-stage cp.async ring, one __syncthreads per chunk; c state in registers.
// Grid (16 ct, 16 mb) = 256 CTAs, 2 per SM, persistent over all 64 steps.
#define NCH 12
#define ATILE_U4 512                    // 2 rbl x 4 k16 x 2 mt x 32 lanes
#define BTILE_U4 1024                   // 4 k16 x 4 wn x 2 q x 32 lanes
#define NSTG 3
#define OFF_A4(s) ((s) * ATILE_U4)
#define OFF_B4(s) (NSTG * ATILE_U4 + (s) * BTILE_U4)
#define OFF_BIAS4 (NSTG * ATILE_U4 + NSTG * BTILE_U4)
#define SMEM_BYTES ((OFF_BIAS4 + 32) * 16)    // 74240
#define NCTAS 256

// chunk schedule: x chunks first, then h chunks
#define ORD(i) ((i) < 4 ? 8 + (i) : (i) - 4)

// ---------------------------------------------------------------------------
// Scratch (device globals)
// ---------------------------------------------------------------------------
__device__ uint4 g_hp[2][(BB / 32) * (HH / 16) * 2 * 32];            // fp16 frag h
__device__ uint4 g_xp[(size_t)(BB / 32) * TT * (DD / 16) * 2 * 32];  // fp16 frag x
__device__ uint4 g_wB[16 * NCH * BTILE_U4];                          // fp16 frag W
__device__ float g_c[BB * HH];
__device__ unsigned g_bar;

__device__ __forceinline__ float sigm(float x) { return 1.0f / (1.0f + __expf(-x)); }

__device__ __forceinline__ uint32_t smem_u32(const void* p) {
    uint32_t a;
    asm("{ .reg .u64 t; cvta.to.shared.u64 t, %1; cvt.u32.u64 %0, t; }" : "=r"(a) : "l"(p));
    return a;
}

__device__ __forceinline__ uint32_t pack_h2(float a, float b) {
    __half2 h = __floats2half2_rn(a, b);
    return *(uint32_t*)&h;
}

__device__ __forceinline__ void mma_f16(float* d, const uint4& a,
                                        uint32_t b0, uint32_t b1) {
    asm volatile(
        "mma.sync.aligned.m16n8k16.row.col.f32.f16.f16.f32 "
        "{%0,%1,%2,%3}, {%4,%5,%6,%7}, {%8,%9}, {%0,%1,%2,%3};"
        : "+f"(d[0]), "+f"(d[1]), "+f"(d[2]), "+f"(d[3])
        : "r"(a.x), "r"(a.y), "r"(a.z), "r"(a.w), "r"(b0), "r"(b1));
}

__device__ __forceinline__ void cp_async16(uint32_t smem_addr, const void* gptr) {
    asm volatile("cp.async.cg.shared.global [%0], [%1], 16;"
                 :: "r"(smem_addr), "l"(gptr));
}
#define CP_COMMIT() asm volatile("cp.async.commit_group;" ::: "memory")
#define CP_WAIT(n)  asm volatile("cp.async.wait_group %0;" :: "n"(n) : "memory")

// ---------------------------------------------------------------------------
// Prep kernels (layouts identical to R10)
// ---------------------------------------------------------------------------
__global__ void prep_weights(const float* __restrict__ W_ih,
                             const float* __restrict__ W_hh) {
    const int ct = blockIdx.x;      // 0..15
    const int c  = blockIdx.y;      // 0..11
    uint4* dst = g_wB + ((size_t)ct * NCH + c) * BTILE_U4;
    for (int idx = threadIdx.x; idx < BTILE_U4; idx += blockDim.x) {
        int lane = idx & 31, q = (idx >> 5) & 1, wn = (idx >> 6) & 3, k16 = idx >> 8;
        int lq = lane >> 2, lr = lane & 3;
        uint32_t v[4];
        #pragma unroll
        for (int s = 0; s < 4; s++) {
            int nt = q * 2 + (s >> 1);
            int hi = s & 1;
            int grow = nt * HH + ct * 32 + wn * 8 + lq;
            int k = c * 64 + k16 * 16 + hi * 8 + lr * 2;
            float w0, w1;
            if (k < HH) {
                w0 = W_hh[(size_t)grow * HH + k];
                w1 = W_hh[(size_t)grow * HH + k + 1];
            } else {
                w0 = W_ih[(size_t)grow * DD + (k - HH)];
                w1 = W_ih[(size_t)grow * DD + (k - HH) + 1];
            }
            v[s] = pack_h2(w0, w1);
        }
        dst[idx] = make_uint4(v[0], v[1], v[2], v[3]);
    }
}

__global__ void prep_x(const float* __restrict__ x) {
    size_t idx = (size_t)blockIdx.x * blockDim.x + threadIdx.x;
    if (idx >= (size_t)(BB / 32) * TT * (DD / 16) * 2 * 32) return;
    int lane = (int)(idx & 31);
    int mt   = (int)((idx >> 5) & 1);
    int k16x = (int)((idx >> 6) & 15);
    int tt   = (int)((idx >> 10) & 63);
    int rowblk = (int)(idx >> 16);
    int lq = lane >> 2, lr = lane & 3;
    uint32_t v[4];
    #pragma unroll
    for (int s = 0; s < 4; s++) {
        int half = s & 1, hi = s >> 1;
        int m = rowblk * 32 + mt * 16 + half * 8 + lq;
        int d = k16x * 16 + hi * 8 + lr * 2;
        const float* src = x + ((size_t)m * TT + tt) * DD + d;
        v[s] = pack_h2(src[0], src[1]);
    }
    g_xp[idx] = make_uint4(v[0], v[1], v[2], v[3]);
}

__global__ void init_states(const float* __restrict__ h0, const float* __restrict__ c0) {
    int i = blockIdx.x * blockDim.x + threadIdx.x;
    if (i == 0) g_bar = 0;
    if (i >= BB * HH) return;
    int m = i / HH, col = i % HH;
    int rowblk = m >> 5, r5 = m & 31;
    int mt = r5 >> 4, half = (r5 >> 3) & 1, lq = r5 & 7;
    int kg = col >> 4, p = col & 15;
    int hi = p >> 3, lr = (p & 7) >> 1, lo = p & 1;
    int s = hi * 2 + half;
    size_t f4 = (((size_t)rowblk * (HH / 16) + kg) * 2 + mt) * 32 + (lq * 4 + lr);
    __half* dst = (__half*)g_hp[0];
    dst[f4 * 8 + s * 2 + lo] = __float2half_rn(h0[i]);
    g_c[i] = c0[i];
}

// ---------------------------------------------------------------------------
// Persistent fused LSTM (fp16 mma, 64x128 CTA tile, 3-stage ring, c in regs).
// ---------------------------------------------------------------------------
__global__ __launch_bounds__(256, 2)
void lstm_persist(const float* __restrict__ b_ih, const float* __restrict__ b_hh,
                  const int* __restrict__ dones, float* __restrict__ out) {
    extern __shared__ uint4 sm4[];
    const uint32_t sb = smem_u32(sm4);
    float* biasS = (float*)(sm4 + OFF_BIAS4);
    const int tid  = threadIdx.x;
    const int wid  = tid >> 5;
    const int lane = tid & 31;
    const int wm   = wid >> 2;           // 0..1 (32 m-rows each)
    const int wn   = wid & 3;            // 0..3 (8 hcols x 4 gates)
    const int ct   = blockIdx.x;         // 0..15
    const int c0   = ct * 32;
    const int m0   = blockIdx.y * 64;    // 0..15 m-tiles
    const int rb0  = m0 >> 5;            // 2 rowblocks per CTA
    const int lq   = lane >> 2;
    const int lr   = lane & 3;

    if (tid < 128) {
        int gate = tid >> 5, hl = tid & 31;
        int col = gate * HH + c0 + hl;
        biasS[tid] = b_ih[col] + b_hh[col];
    }
    __syncthreads();

    // c state in registers: creg[mt][half][ci], fixed (m, colh) ownership.
    const int hl0   = wn * 8 + lr * 2;
    const int colh0 = c0 + hl0;
    float creg[2][2][2];
    #pragma unroll
    for (int mt = 0; mt < 2; mt++)
        #pragma unroll
        for (int half = 0; half < 2; half++) {
            int m = m0 + wm * 32 + mt * 16 + half * 8 + lq;
            float2 v = *(float2*)(g_c + (size_t)m * HH + colh0);
            creg[mt][half][0] = v.x;
            creg[mt][half][1] = v.y;
        }

    for (int t = 0; t < TT; t++) {
        const uint4* __restrict__ hp_in = g_hp[t & 1];
        uint32_t* __restrict__ hp_out   = (uint32_t*)g_hp[(t + 1) & 1];

        // prefetch done-masks for this step (consumed in epilogue)
        float mask2[2][2];
        #pragma unroll
        for (int mt = 0; mt < 2; mt++)
            #pragma unroll
            for (int half = 0; half < 2; half++) {
                int m = m0 + wm * 32 + mt * 16 + half * 8 + lq;
                mask2[mt][half] = (t < TT - 1)
                    ? 1.0f - (float)dones[(size_t)m * TT + t] : 1.0f;
            }

        // loader: A = 2 rowblocks x 256 uint4 (2/thread); B = 1024 uint4 (4/thread)
        auto load_tile = [&](int c, int stage) {
            const uint32_t abase = sb + OFF_A4(stage) * 16;
            const uint32_t bbase = sb + OFF_B4(stage) * 16;
            #pragma unroll
            for (int l = 0; l < 2; l++) {
                int idx = l * 256 + tid;     // 0..511
                int rbl = idx >> 8;
                int rem = idx & 255;
                const uint4* src;
                if (c < 8)
                    src = hp_in + (size_t)(rb0 + rbl) * 2048 + c * 256 + rem;
                else
                    src = g_xp + ((size_t)(rb0 + rbl) * TT + t) * 1024 + (c - 8) * 256 + rem;
                cp_async16(abase + idx * 16, src);
            }
            const uint4* bsrc = g_wB + ((size_t)ct * NCH + c) * BTILE_U4;
            #pragma unroll
            for (int l = 0; l < 4; l++) {
                int idx = l * 256 + tid;
                cp_async16(bbase + idx * 16, bsrc + idx);
            }
            CP_COMMIT();
        };

        float acc[2][4][4];
        #pragma unroll
        for (int mt = 0; mt < 2; mt++)
            #pragma unroll
            for (int nt = 0; nt < 4; nt++)
                #pragma unroll
                for (int i = 0; i < 4; i++) acc[mt][nt][i] = 0.0f;

        // prologue: chunks 8, 9 (x) into stages 0, 1
        load_tile(ORD(0), 0);
        load_tile(ORD(1), 1);

        int stage = 0, stage2 = 2;        // stage = idx%3, stage2 = (idx+2)%3
        #pragma unroll 1
        for (int idx = 0; idx < NCH; idx++) {
            if (idx < NCH - 1) { CP_WAIT(1); } else { CP_WAIT(0); }
            __syncthreads();               // load(idx) visible; compute(idx-1) done

            if (idx == 2) {
                // grid barrier before issuing the first h-chunk load (ORD(4)=0)
                if (tid == 0) {
                    unsigned target = (unsigned)(NCTAS * t);
                    while (*(volatile unsigned*)&g_bar < target) { __nanosleep(64); }
                }
                __syncthreads();
                __threadfence();
            }
            if (idx + 2 < NCH) load_tile(ORD(idx + 2), stage2);

            const uint4* Au = sm4 + OFF_A4(stage);
            const uint4* Bu = sm4 + OFF_B4(stage);
            #pragma unroll
            for (int k16 = 0; k16 < 4; k16++) {
                uint4 a0 = Au[wm * 256 + k16 * 64 + lane];        // mt=0
                uint4 a1 = Au[wm * 256 + k16 * 64 + 32 + lane];   // mt=1
                uint4 b0 = Bu[k16 * 256 + wn * 64 + lane];        // nt 0,1
                uint4 b1 = Bu[k16 * 256 + wn * 64 + 32 + lane];   // nt 2,3
                mma_f16(acc[0][0], a0, b0.x, b0.y);
                mma_f16(acc[0][1], a0, b0.z, b0.w);
                mma_f16(acc[0][2], a0, b1.x, b1.y);
                mma_f16(acc[0][3], a0, b1.z, b1.w);
                mma_f16(acc[1][0], a1, b0.x, b0.y);
                mma_f16(acc[1][1], a1, b0.z, b0.w);
                mma_f16(acc[1][2], a1, b1.x, b1.y);
                mma_f16(acc[1][3], a1, b1.z, b1.w);
            }
            stage  = (stage  == 2) ? 0 : stage + 1;
            stage2 = (stage2 == 2) ? 0 : stage2 + 1;
        }

        // ---- Epilogue (c in registers) ----
        const int kg = ct * 2 + (wn >> 1);
        #pragma unroll
        for (int mt = 0; mt < 2; mt++) {
            #pragma unroll
            for (int half = 0; half < 2; half++) {
                const int m = m0 + wm * 32 + mt * 16 + half * 8 + lq;
                const float maskn = mask2[mt][half];
                float hn2[2];
                #pragma unroll
                for (int ci = 0; ci < 2; ci++) {
                    const int idx = half * 2 + ci;
                    const int hl = hl0 + ci;
                    float gi = acc[mt][0][idx] + biasS[0 * 32 + hl];
                    float gf = acc[mt][1][idx] + biasS[1 * 32 + hl];
                    float gg = acc[mt][2][idx] + biasS[2 * 32 + hl];
                    float go = acc[mt][3][idx] + biasS[3 * 32 + hl];
                    float cp = creg[mt][half][ci];
                    float cn = sigm(gf) * cp + sigm(gi) * tanhf(gg);
                    float hn = sigm(go) * tanhf(cn);
                    creg[mt][half][ci] = cn * maskn;
                    hn2[ci] = hn;
                }
                {
                    int s = (wn & 1) * 2 + half;
                    size_t f4 = (((size_t)(rb0 + wm) * 32 + kg) * 2 + mt) * 32
                                + (lq * 4 + lr);
                    hp_out[f4 * 4 + s] = pack_h2(hn2[0] * maskn, hn2[1] * maskn);
                }
                *(float2*)(out + ((size_t)m * TT + t) * HH + colh0) =
                    make_float2(hn2[0], hn2[1]);
                if (t == TT - 1)
                    *(float2*)(g_c + (size_t)m * HH + colh0) =
                        make_float2(creg[mt][half][0], creg[mt][half][1]);
            }
        }

        __threadfence();
        __syncthreads();
        if (tid == 0) atomicAdd(&g_bar, 1u);
    }
}

// ---------------------------------------------------------------------------
// Copy final states BEFORE LayerNorm: h_n = out[:, T-1, :], c_n = g_c.
// ---------------------------------------------------------------------------
__global__ void copy_states(float* __restrict__ out) {
    int i = blockIdx.x * blockDim.x + threadIdx.x;
    if (i < BB * HH) {
        const size_t base = (size_t)BB * TT * HH;
        int m = i / HH, col = i % HH;
        out[base + i]           = out[((size_t)m * TT + (TT - 1)) * HH + col];
        out[base + BB * HH + i] = g_c[i];
    }
}

// ---------------------------------------------------------------------------
// LayerNorm in-place over H=512. One 128-thread block per row.
// ---------------------------------------------------------------------------
__global__ __launch_bounds__(128)
void ln_kernel(float* __restrict__ out, const float* __restrict__ gamma,
               const float* __restrict__ beta) {
    __shared__ float red[8];
    const int row = blockIdx.x;
    const int tid = threadIdx.x;
    float* p = out + (size_t)row * HH;

    float4 v = ((const float4*)p)[tid];
    float s  = v.x + v.y + v.z + v.w;
    float sq = v.x * v.x + v.y * v.y + v.z * v.z + v.w * v.w;
    #pragma unroll
    for (int o = 16; o > 0; o >>= 1) {
        s  += __shfl_xor_sync(0xFFFFFFFFu, s, o);
        sq += __shfl_xor_sync(0xFFFFFFFFu, sq, o);
    }
    int warp = tid >> 5, lane = tid & 31;
    if (lane == 0) { red[warp] = s; red[4 + warp] = sq; }
    __syncthreads();
    s  = red[0] + red[1] + red[2] + red[3];
    sq = red[4] + red[5] + red[6] + red[7];

    float mu  = s * (1.0f / HH);
    float var = sq * (1.0f / HH) - mu * mu;
    float rr  = rsqrtf(var + LN_EPS);

    float4 gm = ((const float4*)gamma)[tid];
    float4 bt = ((const float4*)beta)[tid];
    float4 y;
    y.x = gm.x * (v.x - mu) * rr + bt.x;
    y.y = gm.y * (v.y - mu) * rr + bt.y;
    y.z = gm.z * (v.z - mu) * rr + bt.z;
    y.w = gm.w * (v.w - mu) * rr + bt.w;
    ((float4*)p)[tid] = y;
}

// ---------------------------------------------------------------------------
// Launch
// ---------------------------------------------------------------------------
extern "C" void kernel_launch(void* const* d_in, const int* in_sizes, int n_in,
                              void* d_out, int out_size) {
    const float* x     = (const float*)d_in[0];
    const float* h0    = (const float*)d_in[1];
    const float* c0    = (const float*)d_in[2];
    const float* W_ih  = (const float*)d_in[3];
    const float* W_hh  = (const float*)d_in[4];
    const float* b_ih  = (const float*)d_in[5];
    const float* b_hh  = (const float*)d_in[6];
    const float* gamma = (const float*)d_in[7];
    const float* beta  = (const float*)d_in[8];
    const int*   dones = (const int*)d_in[9];
    float* out = (float*)d_out;

    cudaFuncSetAttribute(lstm_persist, cudaFuncAttributeMaxDynamicSharedMemorySize,
                         SMEM_BYTES);

    init_states<<<(BB * HH + 255) / 256, 256>>>(h0, c0);
    prep_weights<<<dim3(16, NCH), 256>>>(W_ih, W_hh);
    {
        size_t n = (size_t)(BB / 32) * TT * (DD / 16) * 2 * 32;
        prep_x<<<(int)((n + 255) / 256), 256>>>(x);
    }

    lstm_persist<<<dim3(16, 16), 256, SMEM_BYTES>>>(b_ih, b_hh, dones, out);

    copy_states<<<(BB * HH + 255) / 256, 256>>>(out);
    ln_kernel<<<BB * TT, 128>>>(out, gamma, beta);
}

// round 15
// speedup vs baseline: 1.3963x; 1.1083x over previous
#include <cuda_runtime.h>
#include <cuda_fp16.h>
#include <cstdint>
#include <cstddef>

// Problem constants
#define BB 1024
#define TT 64
#define DD 256
#define HH 512
#define LN_EPS 1e-5f

// Fused step GEMM (fp16 mma m16n8k16): C[64 m, 128 n] per CTA,
// n = 32 hcols x 4 gates. K = 768 in 12 chunks of 64 (4 k16 each).
// 256 threads = 8 warps (wm 0..1 x wn 0..3), warp tile 32m x 32n.
// Chunks 0..7 = h (barrier-dependent), 8..11 = x (independent).
// 3-stage cp.async ring, fully unrolled; c state in registers.
// PER-MB grid barrier: only the 16 ct-CTAs sharing an mb must sync each step,
// so mb-groups pipeline independently across the sequence.
// Grid (16 ct, 16 mb) = 256 CTAs, 2 per SM, persistent over all 64 steps.
#define NCH 12
#define ATILE_U4 512                    // 2 rbl x 4 k16 x 2 mt x 32 lanes
#define BTILE_U4 1024                   // 4 k16 x 4 wn x 2 q x 32 lanes
#define NSTG 3
#define OFF_A4(s) ((s) * ATILE_U4)
#define OFF_B4(s) (NSTG * ATILE_U4 + (s) * BTILE_U4)
#define OFF_BIAS4 (NSTG * ATILE_U4 + NSTG * BTILE_U4)
#define SMEM_BYTES ((OFF_BIAS4 + 32) * 16)    // 74240
#define NMB 16                          // mb groups
#define CTAS_PER_MB 16                  // ct CTAs per group

// chunk schedule: x chunks first, then h chunks
#define ORD(i) ((i) < 4 ? 8 + (i) : (i) - 4)

// ---------------------------------------------------------------------------
// Scratch (device globals)
// ---------------------------------------------------------------------------
__device__ uint4 g_hp[2][(BB / 32) * (HH / 16) * 2 * 32];            // fp16 frag h
__device__ uint4 g_xp[(size_t)(BB / 32) * TT * (DD / 16) * 2 * 32];  // fp16 frag x
__device__ uint4 g_wB[16 * NCH * BTILE_U4];                          // fp16 frag W
__device__ float g_c[BB * HH];
__device__ unsigned g_bar[NMB];

__device__ __forceinline__ float sigm(float x) { return 1.0f / (1.0f + __expf(-x)); }

__device__ __forceinline__ uint32_t smem_u32(const void* p) {
    uint32_t a;
    asm("{ .reg .u64 t; cvta.to.shared.u64 t, %1; cvt.u32.u64 %0, t; }" : "=r"(a) : "l"(p));
    return a;
}

__device__ __forceinline__ uint32_t pack_h2(float a, float b) {
    __half2 h = __floats2half2_rn(a, b);
    return *(uint32_t*)&h;
}

__device__ __forceinline__ void mma_f16(float* d, const uint4& a,
                                        uint32_t b0, uint32_t b1) {
    asm volatile(
        "mma.sync.aligned.m16n8k16.row.col.f32.f16.f16.f32 "
        "{%0,%1,%2,%3}, {%4,%5,%6,%7}, {%8,%9}, {%0,%1,%2,%3};"
        : "+f"(d[0]), "+f"(d[1]), "+f"(d[2]), "+f"(d[3])
        : "r"(a.x), "r"(a.y), "r"(a.z), "r"(a.w), "r"(b0), "r"(b1));
}

__device__ __forceinline__ void cp_async16(uint32_t smem_addr, const void* gptr) {
    asm volatile("cp.async.cg.shared.global [%0], [%1], 16;"
                 :: "r"(smem_addr), "l"(gptr));
}
#define CP_COMMIT() asm volatile("cp.async.commit_group;" ::: "memory")
#define CP_WAIT(n)  asm volatile("cp.async.wait_group %0;" :: "n"(n) : "memory")

// ---------------------------------------------------------------------------
// Prep kernels (layouts identical to R10)
// ---------------------------------------------------------------------------
__global__ void prep_weights(const float* __restrict__ W_ih,
                             const float* __restrict__ W_hh) {
    const int ct = blockIdx.x;      // 0..15
    const int c  = blockIdx.y;      // 0..11
    uint4* dst = g_wB + ((size_t)ct * NCH + c) * BTILE_U4;
    for (int idx = threadIdx.x; idx < BTILE_U4; idx += blockDim.x) {
        int lane = idx & 31, q = (idx >> 5) & 1, wn = (idx >> 6) & 3, k16 = idx >> 8;
        int lq = lane >> 2, lr = lane & 3;
        uint32_t v[4];
        #pragma unroll
        for (int s = 0; s < 4; s++) {
            int nt = q * 2 + (s >> 1);
            int hi = s & 1;
            int grow = nt * HH + ct * 32 + wn * 8 + lq;
            int k = c * 64 + k16 * 16 + hi * 8 + lr * 2;
            float w0, w1;
            if (k < HH) {
                w0 = W_hh[(size_t)grow * HH + k];
                w1 = W_hh[(size_t)grow * HH + k + 1];
            } else {
                w0 = W_ih[(size_t)grow * DD + (k - HH)];
                w1 = W_ih[(size_t)grow * DD + (k - HH) + 1];
            }
            v[s] = pack_h2(w0, w1);
        }
        dst[idx] = make_uint4(v[0], v[1], v[2], v[3]);
    }
}

__global__ void prep_x(const float* __restrict__ x) {
    size_t idx = (size_t)blockIdx.x * blockDim.x + threadIdx.x;
    if (idx >= (size_t)(BB / 32) * TT * (DD / 16) * 2 * 32) return;
    int lane = (int)(idx & 31);
    int mt   = (int)((idx >> 5) & 1);
    int k16x = (int)((idx >> 6) & 15);
    int tt   = (int)((idx >> 10) & 63);
    int rowblk = (int)(idx >> 16);
    int lq = lane >> 2, lr = lane & 3;
    uint32_t v[4];
    #pragma unroll
    for (int s = 0; s < 4; s++) {
        int half = s & 1, hi = s >> 1;
        int m = rowblk * 32 + mt * 16 + half * 8 + lq;
        int d = k16x * 16 + hi * 8 + lr * 2;
        const float* src = x + ((size_t)m * TT + tt) * DD + d;
        v[s] = pack_h2(src[0], src[1]);
    }
    g_xp[idx] = make_uint4(v[0], v[1], v[2], v[3]);
}

__global__ void init_states(const float* __restrict__ h0, const float* __restrict__ c0) {
    int i = blockIdx.x * blockDim.x + threadIdx.x;
    if (i < NMB) g_bar[i] = 0;
    if (i >= BB * HH) return;
    int m = i / HH, col = i % HH;
    int rowblk = m >> 5, r5 = m & 31;
    int mt = r5 >> 4, half = (r5 >> 3) & 1, lq = r5 & 7;
    int kg = col >> 4, p = col & 15;
    int hi = p >> 3, lr = (p & 7) >> 1, lo = p & 1;
    int s = hi * 2 + half;
    size_t f4 = (((size_t)rowblk * (HH / 16) + kg) * 2 + mt) * 32 + (lq * 4 + lr);
    __half* dst = (__half*)g_hp[0];
    dst[f4 * 8 + s * 2 + lo] = __float2half_rn(h0[i]);
    g_c[i] = c0[i];
}

// ---------------------------------------------------------------------------
// Persistent fused LSTM (fp16 mma, 64x128 CTA tile, 3-stage ring, c in regs,
// per-mb barrier, fully unrolled chunk loop).
// ---------------------------------------------------------------------------
__global__ __launch_bounds__(256, 2)
void lstm_persist(const float* __restrict__ b_ih, const float* __restrict__ b_hh,
                  const int* __restrict__ dones, float* __restrict__ out) {
    extern __shared__ uint4 sm4[];
    const uint32_t sb = smem_u32(sm4);
    float* biasS = (float*)(sm4 + OFF_BIAS4);
    const int tid  = threadIdx.x;
    const int wid  = tid >> 5;
    const int lane = tid & 31;
    const int wm   = wid >> 2;           // 0..1 (32 m-rows each)
    const int wn   = wid & 3;            // 0..3 (8 hcols x 4 gates)
    const int ct   = blockIdx.x;         // 0..15
    const int c0   = ct * 32;
    const int mb   = blockIdx.y;         // 0..15
    const int m0   = mb * 64;
    const int rb0  = m0 >> 5;            // 2 rowblocks per CTA
    const int lq   = lane >> 2;
    const int lr   = lane & 3;

    if (tid < 128) {
        int gate = tid >> 5, hl = tid & 31;
        int col = gate * HH + c0 + hl;
        biasS[tid] = b_ih[col] + b_hh[col];
    }
    __syncthreads();

    // Hoisted per-thread loader bases (A: 2 rowblocks at rem = tid)
    const uint4* const hbase0 = g_hp[0] + (size_t)rb0 * 2048 + tid;        // t even
    const uint4* const hbase1 = g_hp[1] + (size_t)rb0 * 2048 + tid;        // t odd
    const uint4* const xbase  = g_xp + (size_t)rb0 * TT * 1024 + tid;
    const uint4* const wbase  = g_wB + (size_t)ct * NCH * BTILE_U4 + tid;
    volatile unsigned* const barp = &g_bar[mb];

    // c state in registers: creg[mt][half][ci], fixed (m, colh) ownership.
    const int hl0   = wn * 8 + lr * 2;
    const int colh0 = c0 + hl0;
    float creg[2][2][2];
    #pragma unroll
    for (int mt = 0; mt < 2; mt++)
        #pragma unroll
        for (int half = 0; half < 2; half++) {
            int m = m0 + wm * 32 + mt * 16 + half * 8 + lq;
            float2 v = *(float2*)(g_c + (size_t)m * HH + colh0);
            creg[mt][half][0] = v.x;
            creg[mt][half][1] = v.y;
        }

    for (int t = 0; t < TT; t++) {
        const uint4* __restrict__ hp_in = (t & 1) ? hbase1 : hbase0;
        uint32_t* __restrict__ hp_out   = (uint32_t*)((t & 1) ? g_hp[0] : g_hp[1]);
        const uint4* __restrict__ xp_t  = xbase + (size_t)t * 1024;

        // prefetch done-masks for this step (consumed in epilogue)
        float mask2[2][2];
        #pragma unroll
        for (int mt = 0; mt < 2; mt++)
            #pragma unroll
            for (int half = 0; half < 2; half++) {
                int m = m0 + wm * 32 + mt * 16 + half * 8 + lq;
                mask2[mt][half] = (t < TT - 1)
                    ? 1.0f - (float)dones[(size_t)m * TT + t] : 1.0f;
            }

        // loader: A = 2 rowblocks (2 cp/thread); B = 1024 uint4 (4 cp/thread)
        auto load_tile = [&](int c, int stage) {
            const uint32_t abase = sb + OFF_A4(stage) * 16;
            const uint32_t bbase = sb + OFF_B4(stage) * 16;
            const uint4* asrc = (c < 8) ? (hp_in + c * 256)
                                        : (xp_t + (c - 8) * 256);
            cp_async16(abase + tid * 16,           asrc);
            cp_async16(abase + (tid + 256) * 16,   asrc + 2048 - tid + (TT * 0) + tid); // rowblock +1
            const uint4* bsrc = wbase + c * BTILE_U4;
            cp_async16(bbase + tid * 16,         bsrc);
            cp_async16(bbase + (tid + 256) * 16, bsrc + 256);
            cp_async16(bbase + (tid + 512) * 16, bsrc + 512);
            cp_async16(bbase + (tid + 768) * 16, bsrc + 768);
            CP_COMMIT();
        };
        // NOTE on A rowblock stride: h stride between rowblocks = 2048 uint4;
        // x stride between rowblocks = TT*1024. Handled explicitly below instead
        // of the broken inline above — define the real loader:
        auto load_tile2 = [&](int c, int stage) {
            const uint32_t abase = sb + OFF_A4(stage) * 16;
            const uint32_t bbase = sb + OFF_B4(stage) * 16;
            if (c < 8) {
                const uint4* asrc = hp_in + c * 256;
                cp_async16(abase + tid * 16,         asrc);
                cp_async16(abase + (tid + 256) * 16, asrc + 2048);
            } else {
                const uint4* asrc = xp_t + (c - 8) * 256;
                cp_async16(abase + tid * 16,         asrc);
                cp_async16(abase + (tid + 256) * 16, asrc + (size_t)TT * 1024);
            }
            const uint4* bsrc = wbase + c * BTILE_U4;
            cp_async16(bbase + tid * 16,         bsrc);
            cp_async16(bbase + (tid + 256) * 16, bsrc + 256);
            cp_async16(bbase + (tid + 512) * 16, bsrc + 512);
            cp_async16(bbase + (tid + 768) * 16, bsrc + 768);
            CP_COMMIT();
        };
        (void)load_tile;

        float acc[2][4][4];
        #pragma unroll
        for (int mt = 0; mt < 2; mt++)
            #pragma unroll
            for (int nt = 0; nt < 4; nt++)
                #pragma unroll
                for (int i = 0; i < 4; i++) acc[mt][nt][i] = 0.0f;

        // prologue: chunks 8, 9 (x) into stages 0, 1
        load_tile2(ORD(0), 0);
        load_tile2(ORD(1), 1);

        #pragma unroll
        for (int idx = 0; idx < NCH; idx++) {
            const int stage  = idx % NSTG;
            const int stage2 = (idx + 2) % NSTG;
            if (idx < NCH - 1) { CP_WAIT(1); } else { CP_WAIT(0); }
            __syncthreads();               // load(idx) visible; compute(idx-1) done

            if (idx == 2) {
                // per-mb barrier before issuing the first h-chunk load (ORD(4)=0)
                if (tid == 0) {
                    unsigned target = (unsigned)(CTAS_PER_MB * t);
                    while (*barp < target) { __nanosleep(64); }
                }
                __syncthreads();
                __threadfence();
            }
            if (idx + 2 < NCH) load_tile2(ORD(idx + 2), stage2);

            const uint4* Au = sm4 + OFF_A4(stage);
            const uint4* Bu = sm4 + OFF_B4(stage);
            #pragma unroll
            for (int k16 = 0; k16 < 4; k16++) {
                uint4 a0 = Au[wm * 256 + k16 * 64 + lane];        // mt=0
                uint4 a1 = Au[wm * 256 + k16 * 64 + 32 + lane];   // mt=1
                uint4 b0 = Bu[k16 * 256 + wn * 64 + lane];        // nt 0,1
                uint4 b1 = Bu[k16 * 256 + wn * 64 + 32 + lane];   // nt 2,3
                mma_f16(acc[0][0], a0, b0.x, b0.y);
                mma_f16(acc[0][1], a0, b0.z, b0.w);
                mma_f16(acc[0][2], a0, b1.x, b1.y);
                mma_f16(acc[0][3], a0, b1.z, b1.w);
                mma_f16(acc[1][0], a1, b0.x, b0.y);
                mma_f16(acc[1][1], a1, b0.z, b0.w);
                mma_f16(acc[1][2], a1, b1.x, b1.y);
                mma_f16(acc[1][3], a1, b1.z, b1.w);
            }
        }

        // ---- Epilogue (c in registers) ----
        const int kg = ct * 2 + (wn >> 1);
        #pragma unroll
        for (int mt = 0; mt < 2; mt++) {
            #pragma unroll
            for (int half = 0; half < 2; half++) {
                const int m = m0 + wm * 32 + mt * 16 + half * 8 + lq;
                const float maskn = mask2[mt][half];
                float hn2[2];
                #pragma unroll
                for (int ci = 0; ci < 2; ci++) {
                    const int idx = half * 2 + ci;
                    const int hl = hl0 + ci;
                    float gi = acc[mt][0][idx] + biasS[0 * 32 + hl];
                    float gf = acc[mt][1][idx] + biasS[1 * 32 + hl];
                    float gg = acc[mt][2][idx] + biasS[2 * 32 + hl];
                    float go = acc[mt][3][idx] + biasS[3 * 32 + hl];
                    float cp = creg[mt][half][ci];
                    float cn = sigm(gf) * cp + sigm(gi) * tanhf(gg);
                    float hn = sigm(go) * tanhf(cn);
                    creg[mt][half][ci] = cn * maskn;
                    hn2[ci] = hn;
                }
                {
                    int s = (wn & 1) * 2 + half;
                    size_t f4 = (((size_t)(rb0 + wm) * 32 + kg) * 2 + mt) * 32
                                + (lq * 4 + lr);
                    hp_out[f4 * 4 + s] = pack_h2(hn2[0] * maskn, hn2[1] * maskn);
                }
                *(float2*)(out + ((size_t)m * TT + t) * HH + colh0) =
                    make_float2(hn2[0], hn2[1]);
                if (t == TT - 1)
                    *(float2*)(g_c + (size_t)m * HH + colh0) =
                        make_float2(creg[mt][half][0], creg[mt][half][1]);
            }
        }

        __threadfence();
        __syncthreads();
        if (tid == 0) atomicAdd(&g_bar[mb], 1u);
    }
}

// ---------------------------------------------------------------------------
// Copy final states BEFORE LayerNorm: h_n = out[:, T-1, :], c_n = g_c.
// ---------------------------------------------------------------------------
__global__ void copy_states(float* __restrict__ out) {
    int i = blockIdx.x * blockDim.x + threadIdx.x;
    if (i < BB * HH) {
        const size_t base = (size_t)BB * TT * HH;
        int m = i / HH, col = i % HH;
        out[base + i]           = out[((size_t)m * TT + (TT - 1)) * HH + col];
        out[base + BB * HH + i] = g_c[i];
    }
}

// ---------------------------------------------------------------------------
// LayerNorm in-place over H=512. One 128-thread block per row.
// ---------------------------------------------------------------------------
__global__ __launch_bounds__(128)
void ln_kernel(float* __restrict__ out, const float* __restrict__ gamma,
               const float* __restrict__ beta) {
    __shared__ float red[8];
    const int row = blockIdx.x;
    const int tid = threadIdx.x;
    float* p = out + (size_t)row * HH;

    float4 v = ((const float4*)p)[tid];
    float s  = v.x + v.y + v.z + v.w;
    float sq = v.x * v.x + v.y * v.y + v.z * v.z + v.w * v.w;
    #pragma unroll
    for (int o = 16; o > 0; o >>= 1) {
        s  += __shfl_xor_sync(0xFFFFFFFFu, s, o);
        sq += __shfl_xor_sync(0xFFFFFFFFu, sq, o);
    }
    int warp = tid >> 5, lane = tid & 31;
    if (lane == 0) { red[warp] = s; red[4 + warp] = sq; }
    __syncthreads();
    s  = red[0] + red[1] + red[2] + red[3];
    sq = red[4] + red[5] + red[6] + red[7];

    float mu  = s * (1.0f / HH);
    float var = sq * (1.0f / HH) - mu * mu;
    float rr  = rsqrtf(var + LN_EPS);

    float4 gm = ((const float4*)gamma)[tid];
    float4 bt = ((const float4*)beta)[tid];
    float4 y;
    y.x = gm.x * (v.x - mu) * rr + bt.x;
    y.y = gm.y * (v.y - mu) * rr + bt.y;
    y.z = gm.z * (v.z - mu) * rr + bt.z;
    y.w = gm.w * (v.w - mu) * rr + bt.w;
    ((float4*)p)[tid] = y;
}

// ---------------------------------------------------------------------------
// Launch
// ---------------------------------------------------------------------------
extern "C" void kernel_launch(void* const* d_in, const int* in_sizes, int n_in,
                              void* d_out, int out_size) {
    const float* x     = (const float*)d_in[0];
    const float* h0    = (const float*)d_in[1];
    const float* c0    = (const float*)d_in[2];
    const float* W_ih  = (const float*)d_in[3];
    const float* W_hh  = (const float*)d_in[4];
    const float* b_ih  = (const float*)d_in[5];
    const float* b_hh  = (const float*)d_in[6];
    const float* gamma = (const float*)d_in[7];
    const float* beta  = (const float*)d_in[8];
    const int*   dones = (const int*)d_in[9];
    float* out = (float*)d_out;

    cudaFuncSetAttribute(lstm_persist, cudaFuncAttributeMaxDynamicSharedMemorySize,
                         SMEM_BYTES);

    init_states<<<(BB * HH + 255) / 256, 256>>>(h0, c0);
    prep_weights<<<dim3(16, NCH), 256>>>(W_ih, W_hh);
    {
        size_t n = (size_t)(BB / 32) * TT * (DD / 16) * 2 * 32;
        prep_x<<<(int)((n + 255) / 256), 256>>>(x);
    }

    lstm_persist<<<dim3(16, 16), 256, SMEM_BYTES>>>(b_ih, b_hh, dones, out);

    copy_states<<<(BB * HH + 255) / 256, 256>>>(out);
    ln_kernel<<<BB * TT, 128>>>(out, gamma, beta);
}